// round 1
// baseline (speedup 1.0000x reference)
#include <cuda_runtime.h>
#include <math.h>

#define NODE 8192
#define NSEQ 192
#define NN   (NODE + NSEQ)   // 8384
#define CC   128
#define BB   2
#define EE   262144

// ---------------- static scratch (no allocations allowed) ----------------
__device__ float g_buf0[BB * NN * CC];
__device__ float g_buf1[BB * NN * CC];
__device__ float g_pi[BB * NN];
__device__ float g_pj[BB * NN];
__device__ float g_dinv_intra[BB * NN];  // (deg_intra+1)^-0.5
__device__ float g_selfnorm[BB * NN];    // 1/(deg_intra+1)
__device__ float g_dinv_inter[BB * NN];  // deg_inter>0 ? 1/deg_inter : 0
__device__ int   g_degA[BB * NN];
__device__ int   g_degE[BB * NN];

// ---------------- preprocessing ----------------
__global__ void k_zero_deg() {
    int t = blockIdx.x * blockDim.x + threadIdx.x;
    if (t < BB * NN) { g_degA[t] = 0; g_degE[t] = 0; }
}

__global__ void k_deg_count(const int* __restrict__ ei) {
    int t = blockIdx.x * blockDim.x + threadIdx.x;
    if (t >= BB * EE) return;
    int b = t / EE, e = t % EE;
    const int* p = ei + (size_t)b * 2 * EE;
    int src = p[e];
    int dst = p[EE + e];
    bool ss = src < NODE, sd = dst < NODE;
    if (ss == sd) atomicAdd(&g_degA[b * NN + dst], 1);
    else          atomicAdd(&g_degE[b * NN + dst], 1);
}

__global__ void k_deg_fin() {
    int t = blockIdx.x * blockDim.x + threadIdx.x;
    if (t >= BB * NN) return;
    float dA = (float)g_degA[t] + 1.0f;
    g_dinv_intra[t] = rsqrtf(dA);
    g_selfnorm[t]   = 1.0f / dA;
    int dE = g_degE[t];
    g_dinv_inter[t] = (dE > 0) ? 1.0f / (float)dE : 0.0f;
}

__global__ void k_copy_in(const float* __restrict__ src, float* __restrict__ dst) {
    int t = blockIdx.x * blockDim.x + threadIdx.x;
    if (t >= BB * NN * (CC / 4)) return;
    ((float4*)dst)[t] = ((const float4*)src)[t];
}

// ---------------- per-layer node projections ----------------
// pi[n] = x[n] . Wi(type(n))  (first-half weights)
// pj[n] = x[n] . Wj(type(n))  (second-half weights)
__global__ void k_proj(const float* __restrict__ x,
                       const float* __restrict__ Wi_s, const float* __restrict__ Wi_t,
                       const float* __restrict__ Wj_s, const float* __restrict__ Wj_t) {
    int w    = (blockIdx.x * blockDim.x + threadIdx.x) >> 5;
    int lane = threadIdx.x & 31;
    if (w >= BB * NN) return;
    int n = w % NN;
    float4 xv = ((const float4*)x)[(size_t)w * 32 + lane];
    const float4* Wi = (const float4*)((n < NODE) ? Wi_s : Wi_t);
    const float4* Wj = (const float4*)((n < NODE) ? Wj_s : Wj_t);
    float4 wi = Wi[lane];
    float4 wj = Wj[lane];
    float si = xv.x * wi.x + xv.y * wi.y + xv.z * wi.z + xv.w * wi.w;
    float sj = xv.x * wj.x + xv.y * wj.y + xv.z * wj.z + xv.w * wj.w;
    #pragma unroll
    for (int o = 16; o; o >>= 1) {
        si += __shfl_xor_sync(0xFFFFFFFFu, si, o);
        sj += __shfl_xor_sync(0xFFFFFFFFu, sj, o);
    }
    if (lane == 0) { g_pi[w] = si; g_pj[w] = sj; }
}

// ---------------- output init (residual + self-loop term) ----------------
__global__ void k_init_out(const float* __restrict__ x, float* __restrict__ out, int intra) {
    int t = blockIdx.x * blockDim.x + threadIdx.x;
    if (t >= BB * NN * (CC / 4)) return;
    int g = t >> 5;   // node index (global over batch)
    float4 xv = ((const float4*)x)[t];
    float s = 1.0f;
    if (intra) {
        float a = tanhf(g_pi[g] + g_pj[g]);
        s = 1.0f + a * g_selfnorm[g];
    }
    float4 o = make_float4(xv.x * s, xv.y * s, xv.z * s, xv.w * s);
    ((float4*)out)[t] = o;
}

// ---------------- edge scatter: out[dst] += coef * x[src] ----------------
// one warp per edge, lane l owns channels [4l, 4l+4)
__global__ void k_scatter(const float* __restrict__ x, const int* __restrict__ ei,
                          float* __restrict__ out, int intra) {
    int w    = (blockIdx.x * blockDim.x + threadIdx.x) >> 5;
    int lane = threadIdx.x & 31;
    if (w >= BB * EE) return;
    int b = w / EE, e = w % EE;
    const int* p = ei + (size_t)b * 2 * EE;
    int src = p[e];
    int dst = p[EE + e];
    bool ss = src < NODE, sd = dst < NODE;
    bool active = intra ? (ss == sd) : (ss != sd);
    if (!active) return;
    int gs = b * NN + src;
    int gd = b * NN + dst;
    float a = tanhf(g_pi[gd] + g_pj[gs]);
    float coef = intra ? a * g_dinv_intra[gs] * g_dinv_intra[gd]
                       : a * g_dinv_inter[gd];
    float4 v = ((const float4*)x)[(size_t)gs * 32 + lane];
    float4 r = make_float4(v.x * coef, v.y * coef, v.z * coef, v.w * coef);
    float* addr = out + (size_t)gd * CC + lane * 4;
    asm volatile("red.global.add.v4.f32 [%0], {%1, %2, %3, %4};"
                 :: "l"(addr), "f"(r.x), "f"(r.y), "f"(r.z), "f"(r.w)
                 : "memory");
}

__global__ void k_relu(float* __restrict__ buf) {
    int t = blockIdx.x * blockDim.x + threadIdx.x;
    if (t >= BB * NN * (CC / 4)) return;
    float4 v = ((float4*)buf)[t];
    v.x = fmaxf(v.x, 0.0f);
    v.y = fmaxf(v.y, 0.0f);
    v.z = fmaxf(v.z, 0.0f);
    v.w = fmaxf(v.w, 0.0f);
    ((float4*)buf)[t] = v;
}

// ---------------- host driver ----------------
static inline int cdiv(int a, int b) { return (a + b - 1) / b; }

extern "C" void kernel_launch(void* const* d_in, const int* in_sizes, int n_in,
                              void* d_out, int out_size) {
    const float* x   = (const float*)d_in[0];
    const int*   ei  = (const int*)d_in[1];
    const float* Wss = (const float*)d_in[2];
    const float* Wtt = (const float*)d_in[3];
    const float* Wst = (const float*)d_in[4];
    const float* Wts = (const float*)d_in[5];
    float* out = (float*)d_out;

    float *b0, *b1;
    cudaGetSymbolAddress((void**)&b0, g_buf0);
    cudaGetSymbolAddress((void**)&b1, g_buf1);

    const int TPB = 256;
    const int nNodeT = BB * NN;                 // node-level threads
    const int nVecT  = BB * NN * (CC / 4);      // float4-level threads
    const int nEdgeT = BB * EE;                 // edge-level threads
    const int nProjT = BB * NN * 32;            // warp-per-node threads
    const int nScatT = BB * EE * 32;            // warp-per-edge threads

    // preprocessing (edges are launch-invariant)
    k_zero_deg<<<cdiv(nNodeT, TPB), TPB>>>();
    k_deg_count<<<cdiv(nEdgeT, TPB), TPB>>>(ei);
    k_deg_fin<<<cdiv(nNodeT, TPB), TPB>>>();
    k_copy_in<<<cdiv(nVecT, TPB), TPB>>>(x, b0);

    // layer schedule: intra(relu), inter(relu), intra(relu), inter(no relu)
    const float* cur = b0;
    for (int li = 0; li < 2; li++) {
        // ---- intra: s-nodes use W_ss, t-nodes use W_tt ----
        {
            const float* W0s = Wss + li * 2 * CC;
            const float* W0t = Wtt + li * 2 * CC;
            float* nxt = (cur == b0) ? b1 : b0;
            k_proj<<<cdiv(nProjT, TPB), TPB>>>(cur, W0s, W0t, W0s + CC, W0t + CC);
            k_init_out<<<cdiv(nVecT, TPB), TPB>>>(cur, nxt, 1);
            k_scatter<<<cdiv(nScatT, TPB), TPB>>>(cur, ei, nxt, 1);
            k_relu<<<cdiv(nVecT, TPB), TPB>>>(nxt);
            cur = nxt;
        }
        // ---- inter: pi[s]=W_ts[:C], pi[t]=W_st[:C]; pj[s]=W_st[C:], pj[t]=W_ts[C:] ----
        {
            const float* Wst0 = Wst + li * 2 * CC;
            const float* Wts0 = Wts + li * 2 * CC;
            bool last = (li == 1);
            float* nxt = last ? out : ((cur == b0) ? b1 : b0);
            k_proj<<<cdiv(nProjT, TPB), TPB>>>(cur, Wts0, Wst0, Wst0 + CC, Wts0 + CC);
            k_init_out<<<cdiv(nVecT, TPB), TPB>>>(cur, nxt, 0);
            k_scatter<<<cdiv(nScatT, TPB), TPB>>>(cur, ei, nxt, 0);
            if (!last) k_relu<<<cdiv(nVecT, TPB), TPB>>>(nxt);
            cur = nxt;
        }
    }
}

// round 2
// speedup vs baseline: 1.7649x; 1.7649x over previous
#include <cuda_runtime.h>
#include <math.h>

#define NODE 8192
#define NSEQ 192
#define NN   (NODE + NSEQ)   // 8384
#define CC   128
#define BB   2
#define EE   262144

// ---------------- static scratch (no allocations allowed) ----------------
__device__ float g_buf0[BB * NN * CC];
__device__ float g_buf1[BB * NN * CC];
__device__ float g_pi[BB * NN];
__device__ float g_pj[BB * NN];
__device__ float g_dinv_intra[BB * NN];  // (deg_intra+1)^-0.5
__device__ float g_selfnorm[BB * NN];    // 1/(deg_intra+1)
__device__ float g_dinv_inter[BB * NN];  // deg_inter>0 ? 1/deg_inter : 0
__device__ int   g_cntA[BB * NN];        // intra in-degree
__device__ int   g_cntE[BB * NN];        // inter in-degree
__device__ int   g_rowptrA[BB * (NN + 1)];
__device__ int   g_curA[BB * NN];        // fill cursors
__device__ int   g_colA[BB * EE];        // intra CSR: src per sorted edge
__device__ int   g_interSrc[BB * EE];    // compact inter edge list
__device__ int   g_interDst[BB * EE];
__device__ int   g_interCnt[BB];

static inline int cdiv(int a, int b) { return (a + b - 1) / b; }

// ---------------- preprocessing ----------------
__global__ void k_zero() {
    int t = blockIdx.x * blockDim.x + threadIdx.x;
    if (t < BB * NN) { g_cntA[t] = 0; g_cntE[t] = 0; }
    if (t < BB) g_interCnt[t] = 0;
}

__global__ void k_count(const int* __restrict__ ei) {
    int t = blockIdx.x * blockDim.x + threadIdx.x;
    if (t >= BB * EE) return;
    int b = t / EE, e = t % EE;
    const int* p = ei + (size_t)b * 2 * EE;
    int src = p[e];
    int dst = p[EE + e];
    bool ss = src < NODE, sd = dst < NODE;
    if (ss == sd) atomicAdd(&g_cntA[b * NN + dst], 1);
    else          atomicAdd(&g_cntE[b * NN + dst], 1);
}

// one block per batch: exclusive scan of g_cntA -> rowptr + cursors,
// plus degree finalization (dinv etc.) in the same pass.
__global__ void k_scan() {
    int b = blockIdx.x;
    __shared__ int sh[1024];
    __shared__ int carry;
    if (threadIdx.x == 0) carry = 0;
    __syncthreads();
    for (int base = 0; base < NN; base += 1024) {
        int i = base + threadIdx.x;
        int v = (i < NN) ? g_cntA[b * NN + i] : 0;
        sh[threadIdx.x] = v;
        __syncthreads();
        #pragma unroll
        for (int off = 1; off < 1024; off <<= 1) {
            int t = (threadIdx.x >= off) ? sh[threadIdx.x - off] : 0;
            __syncthreads();
            sh[threadIdx.x] += t;
            __syncthreads();
        }
        int incl = sh[threadIdx.x];
        if (i < NN) {
            int rp = carry + incl - v;
            g_rowptrA[b * (NN + 1) + i] = rp;
            g_curA[b * NN + i] = rp;
            // degree finalization
            float dA = (float)v + 1.0f;
            g_dinv_intra[b * NN + i] = rsqrtf(dA);
            g_selfnorm[b * NN + i]   = 1.0f / dA;
            int dE = g_cntE[b * NN + i];
            g_dinv_inter[b * NN + i] = (dE > 0) ? 1.0f / (float)dE : 0.0f;
        }
        __syncthreads();
        if (threadIdx.x == 1023) carry += sh[1023];
        __syncthreads();
    }
    if (threadIdx.x == 0) g_rowptrA[b * (NN + 1) + NN] = carry;
}

__global__ void k_fill(const int* __restrict__ ei) {
    int t = blockIdx.x * blockDim.x + threadIdx.x;
    if (t >= BB * EE) return;
    int b = t / EE, e = t % EE;
    const int* p = ei + (size_t)b * 2 * EE;
    int src = p[e];
    int dst = p[EE + e];
    bool ss = src < NODE, sd = dst < NODE;
    if (ss == sd) {
        int pos = atomicAdd(&g_curA[b * NN + dst], 1);
        g_colA[b * EE + pos] = src;
    } else {
        int pos = atomicAdd(&g_interCnt[b], 1);
        g_interSrc[b * EE + pos] = src;
        g_interDst[b * EE + pos] = dst;
    }
}

// ---------------- per-layer node projections ----------------
__global__ void k_proj(const float* __restrict__ x,
                       const float* __restrict__ Wi_s, const float* __restrict__ Wi_t,
                       const float* __restrict__ Wj_s, const float* __restrict__ Wj_t,
                       int relu_in) {
    int w    = (blockIdx.x * blockDim.x + threadIdx.x) >> 5;
    int lane = threadIdx.x & 31;
    if (w >= BB * NN) return;
    int n = w % NN;
    float4 xv = ((const float4*)x)[(size_t)w * 32 + lane];
    if (relu_in) {
        xv.x = fmaxf(xv.x, 0.0f); xv.y = fmaxf(xv.y, 0.0f);
        xv.z = fmaxf(xv.z, 0.0f); xv.w = fmaxf(xv.w, 0.0f);
    }
    const float4* Wi = (const float4*)((n < NODE) ? Wi_s : Wi_t);
    const float4* Wj = (const float4*)((n < NODE) ? Wj_s : Wj_t);
    float4 wi = Wi[lane];
    float4 wj = Wj[lane];
    float si = xv.x * wi.x + xv.y * wi.y + xv.z * wi.z + xv.w * wi.w;
    float sj = xv.x * wj.x + xv.y * wj.y + xv.z * wj.z + xv.w * wj.w;
    #pragma unroll
    for (int o = 16; o; o >>= 1) {
        si += __shfl_xor_sync(0xFFFFFFFFu, si, o);
        sj += __shfl_xor_sync(0xFFFFFFFFu, sj, o);
    }
    if (lane == 0) { g_pi[w] = si; g_pj[w] = sj; }
}

// ---------------- intra: fused gather + self-loop + residual + relu ----------------
// one warp per node; lane l owns channels [4l, 4l+4)
__global__ void k_gather_intra(const float* __restrict__ x, float* __restrict__ out,
                               int relu_in) {
    int w    = (blockIdx.x * blockDim.x + threadIdx.x) >> 5;
    int lane = threadIdx.x & 31;
    if (w >= BB * NN) return;
    int b = w / NN, n = w % NN;
    const float4* x4 = (const float4*)x;
    float4 xv = x4[(size_t)w * 32 + lane];
    if (relu_in) {
        xv.x = fmaxf(xv.x, 0.0f); xv.y = fmaxf(xv.y, 0.0f);
        xv.z = fmaxf(xv.z, 0.0f); xv.w = fmaxf(xv.w, 0.0f);
    }
    float pid   = g_pi[w];
    float dinvd = g_dinv_intra[w];
    float aself = tanhf(pid + g_pj[w]);
    float s = 1.0f + aself * g_selfnorm[w];
    float4 acc = make_float4(xv.x * s, xv.y * s, xv.z * s, xv.w * s);

    int start = g_rowptrA[b * (NN + 1) + n];
    int end   = g_rowptrA[b * (NN + 1) + n + 1];
    for (int e0 = start; e0 < end; e0 += 32) {
        int idx = e0 + lane;
        int src = 0;
        float coef = 0.0f;
        if (idx < end) {
            src = g_colA[b * EE + idx];
            int gs = b * NN + src;
            coef = tanhf(pid + g_pj[gs]) * dinvd * g_dinv_intra[gs];
        }
        int cnt = min(32, end - e0);
        for (int k = 0; k < cnt; k++) {
            float c  = __shfl_sync(0xFFFFFFFFu, coef, k);
            int   sk = __shfl_sync(0xFFFFFFFFu, src, k);
            float4 v = x4[((size_t)(b * NN + sk)) * 32 + lane];
            if (relu_in) {
                v.x = fmaxf(v.x, 0.0f); v.y = fmaxf(v.y, 0.0f);
                v.z = fmaxf(v.z, 0.0f); v.w = fmaxf(v.w, 0.0f);
            }
            acc.x += c * v.x; acc.y += c * v.y;
            acc.z += c * v.z; acc.w += c * v.w;
        }
    }
    // intra layers always relu the output in the schedule
    acc.x = fmaxf(acc.x, 0.0f); acc.y = fmaxf(acc.y, 0.0f);
    acc.z = fmaxf(acc.z, 0.0f); acc.w = fmaxf(acc.w, 0.0f);
    ((float4*)out)[(size_t)w * 32 + lane] = acc;
}

// ---------------- inter: residual init + compact-list scatter ----------------
__global__ void k_init_inter(const float* __restrict__ x, float* __restrict__ out) {
    int t = blockIdx.x * blockDim.x + threadIdx.x;
    if (t >= BB * NN * (CC / 4)) return;
    ((float4*)out)[t] = ((const float4*)x)[t];
}

#define IWARPS 4096   // grid-stride warps per batch
__global__ void k_scatter_inter(const float* __restrict__ x, float* __restrict__ out) {
    int w    = (blockIdx.x * blockDim.x + threadIdx.x) >> 5;
    int lane = threadIdx.x & 31;
    if (w >= BB * IWARPS) return;
    int b = w / IWARPS;
    int cnt = g_interCnt[b];
    for (int e = w % IWARPS; e < cnt; e += IWARPS) {
        int src = g_interSrc[b * EE + e];
        int dst = g_interDst[b * EE + e];
        int gs = b * NN + src;
        int gd = b * NN + dst;
        float coef = tanhf(g_pi[gd] + g_pj[gs]) * g_dinv_inter[gd];
        float4 v = ((const float4*)x)[(size_t)gs * 32 + lane];
        float4 r = make_float4(v.x * coef, v.y * coef, v.z * coef, v.w * coef);
        float* addr = out + (size_t)gd * CC + lane * 4;
        asm volatile("red.global.add.v4.f32 [%0], {%1, %2, %3, %4};"
                     :: "l"(addr), "f"(r.x), "f"(r.y), "f"(r.z), "f"(r.w)
                     : "memory");
    }
}

// ---------------- host driver ----------------
extern "C" void kernel_launch(void* const* d_in, const int* in_sizes, int n_in,
                              void* d_out, int out_size) {
    const float* x   = (const float*)d_in[0];
    const int*   ei  = (const int*)d_in[1];
    const float* Wss = (const float*)d_in[2];
    const float* Wtt = (const float*)d_in[3];
    const float* Wst = (const float*)d_in[4];
    const float* Wts = (const float*)d_in[5];
    float* out = (float*)d_out;

    float *b0, *b1;
    cudaGetSymbolAddress((void**)&b0, g_buf0);
    cudaGetSymbolAddress((void**)&b1, g_buf1);

    const int TPB = 256;
    const int nNodeT = BB * NN;
    const int nVecT  = BB * NN * (CC / 4);
    const int nEdgeT = BB * EE;
    const int nWarpNodeT = BB * NN * 32;
    const int nInterT = BB * IWARPS * 32;

    // --- build CSR + compact inter list (launch-invariant work, cheap) ---
    k_zero<<<cdiv(nNodeT, TPB), TPB>>>();
    k_count<<<cdiv(nEdgeT, TPB), TPB>>>(ei);
    k_scan<<<BB, 1024>>>();
    k_fill<<<cdiv(nEdgeT, TPB), TPB>>>(ei);

    // --- layer 0: intra (relu fused) ---
    k_proj<<<cdiv(nWarpNodeT, TPB), TPB>>>(x, Wss, Wtt, Wss + CC, Wtt + CC, 0);
    k_gather_intra<<<cdiv(nWarpNodeT, TPB), TPB>>>(x, b0, 0);

    // --- layer 0: inter (relu deferred to next layer's reads) ---
    k_proj<<<cdiv(nWarpNodeT, TPB), TPB>>>(b0, Wts, Wst, Wst + CC, Wts + CC, 0);
    k_init_inter<<<cdiv(nVecT, TPB), TPB>>>(b0, b1);
    k_scatter_inter<<<cdiv(nInterT, TPB), TPB>>>(b0, b1);

    // --- layer 1: intra (reads relu(b1) on the fly, relu fused on write) ---
    const float* Wss1 = Wss + 2 * CC;
    const float* Wtt1 = Wtt + 2 * CC;
    k_proj<<<cdiv(nWarpNodeT, TPB), TPB>>>(b1, Wss1, Wtt1, Wss1 + CC, Wtt1 + CC, 1);
    k_gather_intra<<<cdiv(nWarpNodeT, TPB), TPB>>>(b1, b0, 1);

    // --- layer 1: inter (final, no relu) -> d_out ---
    const float* Wst1 = Wst + 2 * CC;
    const float* Wts1 = Wts + 2 * CC;
    k_proj<<<cdiv(nWarpNodeT, TPB), TPB>>>(b0, Wts1, Wst1, Wst1 + CC, Wts1 + CC, 0);
    k_init_inter<<<cdiv(nVecT, TPB), TPB>>>(b0, out);
    k_scatter_inter<<<cdiv(nInterT, TPB), TPB>>>(b0, out);
}

// round 3
// speedup vs baseline: 1.9066x; 1.0803x over previous
#include <cuda_runtime.h>
#include <math.h>

#define NODE 8192
#define NSEQ 192
#define NN   (NODE + NSEQ)   // 8384
#define CC   128
#define BB   2
#define EE   262144
#define BN   (BB * NN)

// ---------------- static scratch (no allocations allowed) ----------------
__device__ float g_buf0[BB * NN * CC];
__device__ float g_buf1[BB * NN * CC];
__device__ float g_pi[2 * BN];           // double-buffered (layer parity)
__device__ float g_pj[2 * BN];
__device__ float g_dinv_intra[BN];       // (deg_intra+1)^-0.5
__device__ float g_selfnorm[BN];         // 1/(deg_intra+1)
__device__ float g_dinv_inter[BN];       // deg_inter>0 ? 1/deg_inter : 0
__device__ int   g_cntA[BN];
__device__ int   g_cntE[BN];
__device__ int   g_rowA[BB * (NN + 1)];
__device__ int   g_rowE[BB * (NN + 1)];
__device__ int   g_curA[BN];
__device__ int   g_curE[BN];
__device__ int   g_colA[BB * EE];        // intra CSR (by dst): src ids
__device__ int   g_colE[BB * EE];        // inter CSR (by dst): src ids

static inline int cdiv(int a, int b) { return (a + b - 1) / b; }

// ---------------- preprocessing ----------------
__global__ void k_zero() {
    int t = blockIdx.x * blockDim.x + threadIdx.x;
    if (t < BN) { g_cntA[t] = 0; g_cntE[t] = 0; }
}

// 4 edges per thread, int4 loads, no-return atomics (RED)
__global__ void k_count(const int* __restrict__ ei) {
    int t = blockIdx.x * blockDim.x + threadIdx.x;
    if (t >= BB * (EE / 4)) return;
    int b = t / (EE / 4), e4 = (t % (EE / 4)) * 4;
    const int* p = ei + (size_t)b * 2 * EE;
    int4 s4 = *(const int4*)(p + e4);
    int4 d4 = *(const int4*)(p + EE + e4);
    int ss[4] = {s4.x, s4.y, s4.z, s4.w};
    int dd[4] = {d4.x, d4.y, d4.z, d4.w};
    #pragma unroll
    for (int k = 0; k < 4; k++) {
        bool same = (ss[k] < NODE) == (dd[k] < NODE);
        atomicAdd(same ? &g_cntA[b * NN + dd[k]] : &g_cntE[b * NN + dd[k]], 1);
    }
}

// one block per batch: exclusive scan of cntA and cntE -> rowptrs, cursors,
// degree finalization.
__global__ void k_scan() {
    int b = blockIdx.x;
    __shared__ int shA[1024], shE[1024];
    __shared__ int carryA, carryE;
    if (threadIdx.x == 0) { carryA = 0; carryE = 0; }
    __syncthreads();
    for (int base = 0; base < NN; base += 1024) {
        int i = base + threadIdx.x;
        int vA = (i < NN) ? g_cntA[b * NN + i] : 0;
        int vE = (i < NN) ? g_cntE[b * NN + i] : 0;
        shA[threadIdx.x] = vA; shE[threadIdx.x] = vE;
        __syncthreads();
        #pragma unroll
        for (int off = 1; off < 1024; off <<= 1) {
            int tA = (threadIdx.x >= off) ? shA[threadIdx.x - off] : 0;
            int tE = (threadIdx.x >= off) ? shE[threadIdx.x - off] : 0;
            __syncthreads();
            shA[threadIdx.x] += tA; shE[threadIdx.x] += tE;
            __syncthreads();
        }
        if (i < NN) {
            int rpA = carryA + shA[threadIdx.x] - vA;
            int rpE = carryE + shE[threadIdx.x] - vE;
            g_rowA[b * (NN + 1) + i] = rpA;  g_curA[b * NN + i] = rpA;
            g_rowE[b * (NN + 1) + i] = rpE;  g_curE[b * NN + i] = rpE;
            float dA = (float)vA + 1.0f;
            g_dinv_intra[b * NN + i] = rsqrtf(dA);
            g_selfnorm[b * NN + i]   = 1.0f / dA;
            g_dinv_inter[b * NN + i] = (vE > 0) ? 1.0f / (float)vE : 0.0f;
        }
        __syncthreads();
        if (threadIdx.x == 1023) { carryA += shA[1023]; carryE += shE[1023]; }
        __syncthreads();
    }
    if (threadIdx.x == 0) {
        g_rowA[b * (NN + 1) + NN] = carryA;
        g_rowE[b * (NN + 1) + NN] = carryE;
    }
}

// 4 edges per thread for atomic MLP
__global__ void k_fill(const int* __restrict__ ei) {
    int t = blockIdx.x * blockDim.x + threadIdx.x;
    if (t >= BB * (EE / 4)) return;
    int b = t / (EE / 4), e4 = (t % (EE / 4)) * 4;
    const int* p = ei + (size_t)b * 2 * EE;
    int4 s4 = *(const int4*)(p + e4);
    int4 d4 = *(const int4*)(p + EE + e4);
    int ss[4] = {s4.x, s4.y, s4.z, s4.w};
    int dd[4] = {d4.x, d4.y, d4.z, d4.w};
    int pos[4]; bool same[4];
    #pragma unroll
    for (int k = 0; k < 4; k++) {
        same[k] = (ss[k] < NODE) == (dd[k] < NODE);
        pos[k] = atomicAdd(same[k] ? &g_curA[b * NN + dd[k]]
                                   : &g_curE[b * NN + dd[k]], 1);
    }
    #pragma unroll
    for (int k = 0; k < 4; k++) {
        (same[k] ? g_colA : g_colE)[b * EE + pos[k]] = ss[k];
    }
}

// ---------------- projection helpers ----------------
__device__ __forceinline__ void proj_epilogue(float4 v, int lane, int n, int w,
                                              const float* Wi_s, const float* Wi_t,
                                              const float* Wj_s, const float* Wj_t,
                                              int wr) {
    const float4* Wi = (const float4*)((n < NODE) ? Wi_s : Wi_t);
    const float4* Wj = (const float4*)((n < NODE) ? Wj_s : Wj_t);
    float4 wi = Wi[lane];
    float4 wj = Wj[lane];
    float si = v.x * wi.x + v.y * wi.y + v.z * wi.z + v.w * wi.w;
    float sj = v.x * wj.x + v.y * wj.y + v.z * wj.z + v.w * wj.w;
    #pragma unroll
    for (int o = 16; o; o >>= 1) {
        si += __shfl_xor_sync(0xFFFFFFFFu, si, o);
        sj += __shfl_xor_sync(0xFFFFFFFFu, sj, o);
    }
    if (lane == 0) { g_pi[wr * BN + w] = si; g_pj[wr * BN + w] = sj; }
}

// standalone proj for layer 0 (reads raw input x)
__global__ void k_proj0(const float* __restrict__ x,
                        const float* __restrict__ Wi_s, const float* __restrict__ Wi_t,
                        const float* __restrict__ Wj_s, const float* __restrict__ Wj_t) {
    int w    = (blockIdx.x * blockDim.x + threadIdx.x) >> 5;
    int lane = threadIdx.x & 31;
    if (w >= BN) return;
    float4 xv = ((const float4*)x)[(size_t)w * 32 + lane];
    proj_epilogue(xv, lane, w % NN, w, Wi_s, Wi_t, Wj_s, Wj_t, 0);
}

// ---------------- intra: gather + self + residual + relu + next-proj ----------------
__global__ void k_intra(const float* __restrict__ x, float* __restrict__ out,
                        int rd, int wr,
                        const float* __restrict__ Wi_s, const float* __restrict__ Wi_t,
                        const float* __restrict__ Wj_s, const float* __restrict__ Wj_t) {
    int w    = (blockIdx.x * blockDim.x + threadIdx.x) >> 5;
    int lane = threadIdx.x & 31;
    if (w >= BN) return;
    int b = w / NN, n = w % NN;
    const float4* x4 = (const float4*)x;
    const float* pj = g_pj + rd * BN;
    float4 xv = x4[(size_t)w * 32 + lane];
    float pid   = g_pi[rd * BN + w];
    float dinvd = g_dinv_intra[w];
    float s = 1.0f + tanhf(pid + pj[w]) * g_selfnorm[w];
    float4 acc = make_float4(xv.x * s, xv.y * s, xv.z * s, xv.w * s);

    int start = g_rowA[b * (NN + 1) + n];
    int end   = g_rowA[b * (NN + 1) + n + 1];
    for (int e0 = start; e0 < end; e0 += 32) {
        int idx = e0 + lane;
        int src = 0; float coef = 0.0f;
        if (idx < end) {
            src = g_colA[b * EE + idx];
            int gs = b * NN + src;
            coef = tanhf(pid + pj[gs]) * dinvd * g_dinv_intra[gs];
        }
        int cnt = min(32, end - e0);
        #pragma unroll 4
        for (int k = 0; k < cnt; k++) {
            float c  = __shfl_sync(0xFFFFFFFFu, coef, k);
            int   sk = __shfl_sync(0xFFFFFFFFu, src, k);
            float4 v = x4[((size_t)(b * NN + sk)) * 32 + lane];
            acc.x += c * v.x; acc.y += c * v.y;
            acc.z += c * v.z; acc.w += c * v.w;
        }
    }
    // intra outputs are always relu'd in the schedule
    acc.x = fmaxf(acc.x, 0.0f); acc.y = fmaxf(acc.y, 0.0f);
    acc.z = fmaxf(acc.z, 0.0f); acc.w = fmaxf(acc.w, 0.0f);
    ((float4*)out)[(size_t)w * 32 + lane] = acc;
    proj_epilogue(acc, lane, n, w, Wi_s, Wi_t, Wj_s, Wj_t, wr);
}

// ---------------- inter: gather + residual (+relu, +next-proj) ----------------
__global__ void k_inter(const float* __restrict__ x, float* __restrict__ out,
                        int rd, int wr, int relu_epi,
                        const float* __restrict__ Wi_s, const float* __restrict__ Wi_t,
                        const float* __restrict__ Wj_s, const float* __restrict__ Wj_t) {
    int w    = (blockIdx.x * blockDim.x + threadIdx.x) >> 5;
    int lane = threadIdx.x & 31;
    if (w >= BN) return;
    int b = w / NN, n = w % NN;
    const float4* x4 = (const float4*)x;
    const float* pj = g_pj + rd * BN;
    float4 acc = x4[(size_t)w * 32 + lane];

    int start = g_rowE[b * (NN + 1) + n];
    int end   = g_rowE[b * (NN + 1) + n + 1];
    if (start < end) {
        float pid  = g_pi[rd * BN + w];
        float dinv = g_dinv_inter[w];
        for (int e0 = start; e0 < end; e0 += 32) {
            int idx = e0 + lane;
            int src = 0; float coef = 0.0f;
            if (idx < end) {
                src = g_colE[b * EE + idx];
                coef = tanhf(pid + pj[b * NN + src]) * dinv;
            }
            int cnt = min(32, end - e0);
            #pragma unroll 4
            for (int k = 0; k < cnt; k++) {
                float c  = __shfl_sync(0xFFFFFFFFu, coef, k);
                int   sk = __shfl_sync(0xFFFFFFFFu, src, k);
                float4 v = x4[((size_t)(b * NN + sk)) * 32 + lane];
                acc.x += c * v.x; acc.y += c * v.y;
                acc.z += c * v.z; acc.w += c * v.w;
            }
        }
    }
    if (relu_epi) {
        acc.x = fmaxf(acc.x, 0.0f); acc.y = fmaxf(acc.y, 0.0f);
        acc.z = fmaxf(acc.z, 0.0f); acc.w = fmaxf(acc.w, 0.0f);
    }
    ((float4*)out)[(size_t)w * 32 + lane] = acc;
    if (relu_epi)
        proj_epilogue(acc, lane, n, w, Wi_s, Wi_t, Wj_s, Wj_t, wr);
}

// ---------------- host driver ----------------
extern "C" void kernel_launch(void* const* d_in, const int* in_sizes, int n_in,
                              void* d_out, int out_size) {
    const float* x   = (const float*)d_in[0];
    const int*   ei  = (const int*)d_in[1];
    const float* Wss = (const float*)d_in[2];
    const float* Wtt = (const float*)d_in[3];
    const float* Wst = (const float*)d_in[4];
    const float* Wts = (const float*)d_in[5];
    float* out = (float*)d_out;

    float *b0, *b1;
    cudaGetSymbolAddress((void**)&b0, g_buf0);
    cudaGetSymbolAddress((void**)&b1, g_buf1);

    const int TPB = 256;
    const int nNodeT = BN;
    const int nQuadT = BB * (EE / 4);
    const int nWarpT = BN * 32;

    const float* Wss1 = Wss + 2 * CC;
    const float* Wtt1 = Wtt + 2 * CC;
    const float* Wst1 = Wst + 2 * CC;
    const float* Wts1 = Wts + 2 * CC;

    // --- build CSRs (launch-invariant structure) ---
    k_zero <<<cdiv(nNodeT, TPB), TPB>>>();
    k_count<<<cdiv(nQuadT, TPB), TPB>>>(ei);
    k_scan <<<BB, 1024>>>();
    k_fill <<<cdiv(nQuadT, TPB), TPB>>>(ei);

    // --- layer 0 projections (intra0 weights), parity 0 ---
    k_proj0<<<cdiv(nWarpT, TPB), TPB>>>(x, Wss, Wtt, Wss + CC, Wtt + CC);

    // intra0: read parity 0, write parity 1 (inter0 weights)
    k_intra<<<cdiv(nWarpT, TPB), TPB>>>(x, b0, 0, 1,
                                        Wts, Wst, Wst + CC, Wts + CC);
    // inter0 (+relu): read 1, write 0 (intra1 weights)
    k_inter<<<cdiv(nWarpT, TPB), TPB>>>(b0, b1, 1, 0, 1,
                                        Wss1, Wtt1, Wss1 + CC, Wtt1 + CC);
    // intra1: read 0, write 1 (inter1 weights)
    k_intra<<<cdiv(nWarpT, TPB), TPB>>>(b1, b0, 0, 1,
                                        Wts1, Wst1, Wst1 + CC, Wts1 + CC);
    // inter1 (final, no relu, no epilogue) -> d_out
    k_inter<<<cdiv(nWarpT, TPB), TPB>>>(b0, out, 1, 0, 0,
                                        Wss, Wtt, Wss, Wtt);
}